// round 16
// baseline (speedup 1.0000x reference)
#include <cuda_runtime.h>
#include <cuda_bf16.h>
#include <cstdint>

// ---------------------------------------------------------------------------
// OnlineLSTM (round 16 = round 15 + GEMM 8x16 micro-tile):
//   Phase 1: xg = inp @ W_ih^T + b_ih  (FFMA2 SGEMM, 8x16 micro-tile:
//            0.75 B/FMA breaks the smem-crossbar/FMA balance point)
//   Phase 2: persistent recurrence (R15 verbatim): W_hh in registers,
//            counter barrier, fc folded into CTA-0 tail.
// ---------------------------------------------------------------------------

#define WINDOW  2048
#define ISZ     4096
#define HID     1024
#define GATE4   4096      // 4*HID
#define METRIC  32
#define NCTA    128       // persistent CTAs
#define UPB     8         // hidden units per CTA (NCTA*UPB = HID)

// Scratch (no cudaMalloc allowed)
__device__ float g_xg[WINDOW * GATE4];          // 32 MB
__device__ float g_h[2][HID];
__device__ int   g_cnt;                          // monotonic barrier counter

// ===========================================================================
// GEMM: C[t][r] = sum_k inp[t][k] * W_ih[r][k] + b_ih[r]
// 128x128 tile, BK=8, 128 threads, 8x16 micro-tile via fma.rn.f32x2.
// Double-buffered SMEM, one __syncthreads per K-tile.
// Per K-step/SM (8 warps): fma 256 cyc vs smem ~192 cyc -> fma-bound ~75%.
// ===========================================================================
#define BM 128
#define BN 128
#define BK 8
#define LDT (BM + 4)   // 132 floats, 528B row stride (16B multiple)

__device__ __forceinline__ unsigned long long dup_f32x2(float a) {
    unsigned long long r;
    unsigned int ai = __float_as_uint(a);
    asm("mov.b64 %0, {%1, %1};" : "=l"(r) : "r"(ai));
    return r;
}
__device__ __forceinline__ void fma2(unsigned long long& acc,
                                     unsigned long long a,
                                     unsigned long long b) {
    asm("fma.rn.f32x2 %0, %1, %2, %0;" : "+l"(acc) : "l"(a), "l"(b));
}

__global__ void __launch_bounds__(128, 2) gemm_xg_kernel(
    const float* __restrict__ A,      // inp [2048,4096]
    const float* __restrict__ B,      // W_ih [4096,4096]
    const float* __restrict__ bias,   // b_ih [4096]
    float* __restrict__ C)            // g_xg [2048,4096]
{
    __shared__ __align__(16) float As[2][BK][LDT];
    __shared__ __align__(16) float Bs[2][BK][LDT];

    const int tid = threadIdx.x;      // 0..127
    const int bm = blockIdx.y * BM;
    const int bn = blockIdx.x * BN;

    // loader: thread owns one row of each tile (8 floats = 2 float4 per array)
    const int lr = tid;
    const float* Aptr = A + (size_t)(bm + lr) * ISZ;
    const float* Bptr = B + (size_t)(bn + lr) * ISZ;

    // compute mapping: 8 rows x 16 cols per thread
    const int tx = tid & 7;           // col block: 16 cols at tx*16
    const int ty = tid >> 3;          // row block: 8 rows at ty*8

    unsigned long long acc2[8][8];
#pragma unroll
    for (int i = 0; i < 8; i++)
#pragma unroll
        for (int j = 0; j < 8; j++) acc2[i][j] = 0ull;

    // prologue: fill buffer 0
    {
        float4 a0 = *(const float4*)(Aptr);
        float4 a1 = *(const float4*)(Aptr + 4);
        float4 b0 = *(const float4*)(Bptr);
        float4 b1 = *(const float4*)(Bptr + 4);
        As[0][0][lr] = a0.x; As[0][1][lr] = a0.y; As[0][2][lr] = a0.z; As[0][3][lr] = a0.w;
        As[0][4][lr] = a1.x; As[0][5][lr] = a1.y; As[0][6][lr] = a1.z; As[0][7][lr] = a1.w;
        Bs[0][0][lr] = b0.x; Bs[0][1][lr] = b0.y; Bs[0][2][lr] = b0.z; Bs[0][3][lr] = b0.w;
        Bs[0][4][lr] = b1.x; Bs[0][5][lr] = b1.y; Bs[0][6][lr] = b1.z; Bs[0][7][lr] = b1.w;
    }
    __syncthreads();

    for (int k0 = 0; k0 < ISZ; k0 += BK) {
        const int cur = (k0 >> 3) & 1;
        const bool more = (k0 + BK < ISZ);

        // prefetch next tile from global (issued before compute)
        float4 an0, an1, bn0, bn1;
        if (more) {
            an0 = *(const float4*)(Aptr + k0 + BK);
            an1 = *(const float4*)(Aptr + k0 + BK + 4);
            bn0 = *(const float4*)(Bptr + k0 + BK);
            bn1 = *(const float4*)(Bptr + k0 + BK + 4);
        }

        // compute on buffer `cur`: 8 kk x (8x16 micro-tile)
#pragma unroll
        for (int kk = 0; kk < BK; kk++) {
            float4 a0 = *(const float4*)&As[cur][kk][ty * 8];
            float4 a1 = *(const float4*)&As[cur][kk][ty * 8 + 4];
            ulonglong2 bq0 = *(const ulonglong2*)&Bs[cur][kk][tx * 16];
            ulonglong2 bq1 = *(const ulonglong2*)&Bs[cur][kk][tx * 16 + 4];
            ulonglong2 bq2 = *(const ulonglong2*)&Bs[cur][kk][tx * 16 + 8];
            ulonglong2 bq3 = *(const ulonglong2*)&Bs[cur][kk][tx * 16 + 12];
            unsigned long long b2[8] = {bq0.x, bq0.y, bq1.x, bq1.y,
                                        bq2.x, bq2.y, bq3.x, bq3.y};
            float a[8] = {a0.x, a0.y, a0.z, a0.w, a1.x, a1.y, a1.z, a1.w};
#pragma unroll
            for (int i = 0; i < 8; i++) {
                unsigned long long ad = dup_f32x2(a[i]);
#pragma unroll
                for (int j = 0; j < 8; j++) fma2(acc2[i][j], ad, b2[j]);
            }
        }

        // stage next tile into the other buffer; single sync per K-tile
        if (more) {
            const int nxt = cur ^ 1;
            As[nxt][0][lr] = an0.x; As[nxt][1][lr] = an0.y;
            As[nxt][2][lr] = an0.z; As[nxt][3][lr] = an0.w;
            As[nxt][4][lr] = an1.x; As[nxt][5][lr] = an1.y;
            As[nxt][6][lr] = an1.z; As[nxt][7][lr] = an1.w;
            Bs[nxt][0][lr] = bn0.x; Bs[nxt][1][lr] = bn0.y;
            Bs[nxt][2][lr] = bn0.z; Bs[nxt][3][lr] = bn0.w;
            Bs[nxt][4][lr] = bn1.x; Bs[nxt][5][lr] = bn1.y;
            Bs[nxt][6][lr] = bn1.z; Bs[nxt][7][lr] = bn1.w;
            __syncthreads();
        }
    }

    // epilogue: add bias, store 8 rows x 16 cols
    float bcol[16];
#pragma unroll
    for (int j = 0; j < 16; j++) bcol[j] = bias[bn + tx * 16 + j];

#pragma unroll
    for (int i = 0; i < 8; i++) {
        float* crow = C + (size_t)(bm + ty * 8 + i) * GATE4 + bn + tx * 16;
#pragma unroll
        for (int j = 0; j < 8; j++) {
            unsigned int lo, hi;
            asm("mov.b64 {%0, %1}, %2;" : "=r"(lo), "=r"(hi) : "l"(acc2[i][j]));
            crow[2 * j]     = __uint_as_float(lo) + bcol[2 * j];
            crow[2 * j + 1] = __uint_as_float(hi) + bcol[2 * j + 1];
        }
    }
}

// ===========================================================================
// Init: reset barrier counter, seed h buffer (proven)
// ===========================================================================
__global__ void init_kernel(const float* __restrict__ h1) {
    int i = threadIdx.x;   // 1024 threads
    if (i == 0) g_cnt = 0;
    g_h[0][i] = h1[i];
}

// ===========================================================================
// Barrier primitives (proven)
// ===========================================================================
__device__ __forceinline__ void red_release_add1(int* p) {
    asm volatile("red.release.gpu.global.add.s32 [%0], 1;" :: "l"(p) : "memory");
}
__device__ __forceinline__ int ld_acquire(const int* p) {
    int v;
    asm volatile("ld.acquire.gpu.global.b32 %0, [%1];" : "=r"(v) : "l"(p) : "memory");
    return v;
}

// Fast saturating activations (exact at +-inf; rel err ~1e-6)
__device__ __forceinline__ float sig_fast(float x) {
    return __fdividef(1.0f, 1.0f + __expf(-x));
}
__device__ __forceinline__ float tanh_fast(float x) {
    return 1.0f - __fdividef(2.0f, __expf(2.0f * x) + 1.0f);
}

// ===========================================================================
// Persistent LSTM recurrence (R15 verbatim). 128 CTAs x 512 threads;
// W_hh in registers; per-warp h slab loads; 2-acc dot; counter barrier;
// CTA-0 fc tail.
// ===========================================================================
__global__ void __launch_bounds__(512, 1) lstm_rec_kernel(
    const float* __restrict__ W_hh,   // [4096,1024]
    const float* __restrict__ c1,     // [1024]
    const float* __restrict__ b_hh,   // [4096]
    const float* __restrict__ fc_w,   // [32,1024]
    const float* __restrict__ fc_b,   // [32]
    float* __restrict__ out,          // d_out
    int writeHC)
{
    __shared__ __align__(16) float hsm[HID];
    __shared__ float psum[16][33];

    const int tid = threadIdx.x;
    const int bid = blockIdx.x;
    const int w = tid >> 5;
    const int l = tid & 31;
    const int u = l >> 2;
    const int g = l & 3;
    const int gate_row = g * HID + bid * UPB + u;

    // ---- W_hh slab into registers: 32 f32x2 per thread ----
    unsigned long long wreg[32];
    {
        const float* wp = W_hh + (size_t)gate_row * HID + w * 64;
#pragma unroll
        for (int k = 0; k < 32; k++)
            wreg[k] = *(const unsigned long long*)(wp + 2 * k);
    }

    // ---- warp-0 per-lane state ----
    float bias = 0.f, xg = 0.f, c = 0.f;
    if (w == 0) {
        bias = b_hh[gate_row];
        xg   = __ldg(g_xg + gate_row);       // row t=0
        if (g == 0) c = c1[bid * UPB + u];
    }
    __syncthreads();

    for (int t = 0; t < WINDOW; t++) {
        const int p = t & 1;

        // ---- each warp loads its OWN 64-float h slab (no block sync) ----
        if (l < 16)
            ((float4*)(hsm + w * 64))[l] =
                __ldcg(((const float4*)g_h[p]) + w * 16 + l);
        __syncwarp();

        // ---- 64-col partial dot: 2 accumulators ----
        unsigned long long acc0 = 0ull, acc1 = 0ull;
        const unsigned long long* hp = (const unsigned long long*)(hsm + w * 64);
#pragma unroll
        for (int k = 0; k < 16; k++) {
            fma2(acc0, wreg[2 * k],     hp[2 * k]);
            fma2(acc1, wreg[2 * k + 1], hp[2 * k + 1]);
        }
        {
            unsigned int x0, y0, x1, y1;
            asm("mov.b64 {%0, %1}, %2;" : "=r"(x0), "=r"(y0) : "l"(acc0));
            asm("mov.b64 {%0, %1}, %2;" : "=r"(x1), "=r"(y1) : "l"(acc1));
            psum[w][l] = (__uint_as_float(x0) + __uint_as_float(y0))
                       + (__uint_as_float(x1) + __uint_as_float(y1));
        }
        __syncthreads();

        // ---- warp 0: serial reduce, fast gates, h store ----
        if (w == 0) {
            float pre = xg + bias;
#pragma unroll
            for (int q = 0; q < 16; q++) pre += psum[q][l];

            float a = (g == 2) ? tanh_fast(pre) : sig_fast(pre);
            int base = l & ~3;
            float fg = __shfl_sync(0xffffffffu, a, base + 1);
            float gb = __shfl_sync(0xffffffffu, a, base + 2);
            float og = __shfl_sync(0xffffffffu, a, base + 3);
            if (g == 0) {
                c = fg * c + a * gb;
                float hn = og * tanh_fast(c);
                int jj = bid * UPB + u;
                g_h[p ^ 1][jj] = hn;
                if (writeHC && t == 1023) {          // STRIDE-1
                    out[METRIC + jj] = hn;
                    out[METRIC + HID + jj] = c;
                }
            }
            // prefetch next step's xg (hides L2 latency under the barrier)
            if (t + 1 < WINDOW)
                xg = __ldg(g_xg + (size_t)(t + 1) * GATE4 + gate_row);
        }
        __syncthreads();

        // ---- grid barrier: release-RED arrival + tid0 acquire poll ----
        if (tid == 0) {
            red_release_add1(&g_cnt);
            const int target = (t + 1) * NCTA;
            while (ld_acquire(&g_cnt) < target) { }
        }
        __syncthreads();
    }

    // ---- fc epilogue folded in: CTA 0 only, h_fin = g_h[0] ----
    if (bid == 0) {
        for (int half = 0; half < 2; half++) {
            const int m = 2 * w + half;              // metric 0..31
            const float4* wv = (const float4*)(fc_w + (size_t)m * HID);
            float s = 0.f;
#pragma unroll
            for (int jj = 0; jj < 8; jj++) {
                float4 a = __ldcg(((const float4*)g_h[0]) + l + 32 * jj);
                float4 b = __ldg(wv + l + 32 * jj);
                s += a.x * b.x + a.y * b.y + a.z * b.z + a.w * b.w;
            }
#pragma unroll
            for (int off = 16; off; off >>= 1)
                s += __shfl_xor_sync(0xffffffffu, s, off);
            if (l == 0) out[m] = tanhf(s + fc_b[m]);
        }
    }
}

// ===========================================================================
// launch — exactly 3 launches per call (gemm, init, lstm)
// ===========================================================================
extern "C" void kernel_launch(void* const* d_in, const int* in_sizes, int n_in,
                              void* d_out, int out_size) {
    const float* inp  = (const float*)d_in[0];
    const float* h1   = (const float*)d_in[1];
    const float* c1   = (const float*)d_in[2];
    const float* W_ih = (const float*)d_in[3];
    const float* W_hh = (const float*)d_in[4];
    const float* b_ih = (const float*)d_in[5];
    const float* b_hh = (const float*)d_in[6];
    const float* fc_w = (const float*)d_in[7];
    const float* fc_b = (const float*)d_in[8];
    float* out = (float*)d_out;

    int writeHC = (out_size >= METRIC + 2 * HID) ? 1 : 0;

    float* xg_ptr = nullptr;
    cudaGetSymbolAddress((void**)&xg_ptr, g_xg);

    // Phase 1: xg GEMM (8x16 micro-tile, double-buffered)
    dim3 ggrid(GATE4 / BN, WINDOW / BM);
    gemm_xg_kernel<<<ggrid, 128>>>(inp, W_ih, b_ih, xg_ptr);

    // Phase 1b: init h buffer + barrier counter
    init_kernel<<<1, HID>>>(h1);

    // Phase 2: persistent recurrence + folded fc epilogue
    lstm_rec_kernel<<<NCTA, 512>>>(W_hh, c1, b_hh, fc_w, fc_b, out, writeHC);
}

// round 17
// speedup vs baseline: 1.2222x; 1.2222x over previous
#include <cuda_runtime.h>
#include <cuda_bf16.h>
#include <cstdint>

// ---------------------------------------------------------------------------
// OnlineLSTM (round 17 = round 15 GEMM verbatim + 2-sync recurrence step):
//   Phase 1: xg = inp @ W_ih^T + b_ih  (FFMA2 SGEMM 8x8/256thr, ping-pong —
//            R16's 8x16 regressed: 204 regs, 8 warps/SM, occ 11%)
//   Phase 2: persistent recurrence, W_hh in registers, counter barrier;
//            middle __syncthreads replaced by warp-0 __syncwarp (hb chain:
//            lane stores -> syncwarp -> tid0 release-RED -> consumer acquire).
// ---------------------------------------------------------------------------

#define WINDOW  2048
#define ISZ     4096
#define HID     1024
#define GATE4   4096      // 4*HID
#define METRIC  32
#define NCTA    128       // persistent CTAs
#define UPB     8         // hidden units per CTA (NCTA*UPB = HID)

// Scratch (no cudaMalloc allowed)
__device__ float g_xg[WINDOW * GATE4];          // 32 MB
__device__ float g_h[2][HID];
__device__ int   g_cnt;                          // monotonic barrier counter

// ===========================================================================
// GEMM: C[t][r] = sum_k inp[t][k] * W_ih[r][k] + b_ih[r]
// 128x128 tile, BK=8, 256 threads, 8x8 micro-tile via fma.rn.f32x2.
// Double-buffered SMEM, one __syncthreads per K-tile.  (R15 verbatim)
// ===========================================================================
#define BM 128
#define BN 128
#define BK 8
#define LDT (BM + 4)

__device__ __forceinline__ unsigned long long dup_f32x2(float a) {
    unsigned long long r;
    unsigned int ai = __float_as_uint(a);
    asm("mov.b64 %0, {%1, %1};" : "=l"(r) : "r"(ai));
    return r;
}
__device__ __forceinline__ void fma2(unsigned long long& acc,
                                     unsigned long long a,
                                     unsigned long long b) {
    asm("fma.rn.f32x2 %0, %1, %2, %0;" : "+l"(acc) : "l"(a), "l"(b));
}

__global__ void __launch_bounds__(256, 2) gemm_xg_kernel(
    const float* __restrict__ A,      // inp [2048,4096]
    const float* __restrict__ B,      // W_ih [4096,4096]
    const float* __restrict__ bias,   // b_ih [4096]
    float* __restrict__ C)            // g_xg [2048,4096]
{
    __shared__ __align__(16) float As[2][BK][LDT];
    __shared__ __align__(16) float Bs[2][BK][LDT];

    const int tid = threadIdx.x;
    const int bm = blockIdx.y * BM;
    const int bn = blockIdx.x * BN;

    const int lr = tid >> 1;          // 0..127 row within tile
    const int lk = (tid & 1) * 4;     // 0 or 4
    const float* Aptr = A + (size_t)(bm + lr) * ISZ + lk;
    const float* Bptr = B + (size_t)(bn + lr) * ISZ + lk;

    const int tx = tid & 15;          // n dim
    const int ty = tid >> 4;          // m dim

    unsigned long long acc2[8][4];
#pragma unroll
    for (int i = 0; i < 8; i++)
#pragma unroll
        for (int j = 0; j < 4; j++) acc2[i][j] = 0ull;

    // prologue: fill buffer 0
    {
        float4 av = *(const float4*)(Aptr);
        float4 bv = *(const float4*)(Bptr);
        As[0][lk + 0][lr] = av.x; As[0][lk + 1][lr] = av.y;
        As[0][lk + 2][lr] = av.z; As[0][lk + 3][lr] = av.w;
        Bs[0][lk + 0][lr] = bv.x; Bs[0][lk + 1][lr] = bv.y;
        Bs[0][lk + 2][lr] = bv.z; Bs[0][lk + 3][lr] = bv.w;
    }
    __syncthreads();

    for (int k0 = 0; k0 < ISZ; k0 += BK) {
        const int cur = (k0 >> 3) & 1;
        const bool more = (k0 + BK < ISZ);

        // prefetch next tile from global (issued before compute)
        float4 avn, bvn;
        if (more) {
            avn = *(const float4*)(Aptr + k0 + BK);
            bvn = *(const float4*)(Bptr + k0 + BK);
        }

        // compute on buffer `cur`
#pragma unroll
        for (int kk = 0; kk < BK; kk++) {
            float4 a0 = *(const float4*)&As[cur][kk][ty * 8];
            float4 a1 = *(const float4*)&As[cur][kk][ty * 8 + 4];
            ulonglong2 bq0 = *(const ulonglong2*)&Bs[cur][kk][tx * 8];
            ulonglong2 bq1 = *(const ulonglong2*)&Bs[cur][kk][tx * 8 + 4];
            unsigned long long b2[4] = {bq0.x, bq0.y, bq1.x, bq1.y};
            float a[8] = {a0.x, a0.y, a0.z, a0.w, a1.x, a1.y, a1.z, a1.w};
#pragma unroll
            for (int i = 0; i < 8; i++) {
                unsigned long long ad = dup_f32x2(a[i]);
#pragma unroll
                for (int j = 0; j < 4; j++) fma2(acc2[i][j], ad, b2[j]);
            }
        }

        // stage next tile into the other buffer; single sync per K-tile
        if (more) {
            const int nxt = cur ^ 1;
            As[nxt][lk + 0][lr] = avn.x; As[nxt][lk + 1][lr] = avn.y;
            As[nxt][lk + 2][lr] = avn.z; As[nxt][lk + 3][lr] = avn.w;
            Bs[nxt][lk + 0][lr] = bvn.x; Bs[nxt][lk + 1][lr] = bvn.y;
            Bs[nxt][lk + 2][lr] = bvn.z; Bs[nxt][lk + 3][lr] = bvn.w;
            __syncthreads();
        }
    }

    float bcol[8];
#pragma unroll
    for (int j = 0; j < 8; j++) bcol[j] = bias[bn + tx * 8 + j];

#pragma unroll
    for (int i = 0; i < 8; i++) {
        float* crow = C + (size_t)(bm + ty * 8 + i) * GATE4 + bn + tx * 8;
#pragma unroll
        for (int j = 0; j < 4; j++) {
            unsigned int lo, hi;
            asm("mov.b64 {%0, %1}, %2;" : "=r"(lo), "=r"(hi) : "l"(acc2[i][j]));
            crow[2 * j]     = __uint_as_float(lo) + bcol[2 * j];
            crow[2 * j + 1] = __uint_as_float(hi) + bcol[2 * j + 1];
        }
    }
}

// ===========================================================================
// Init: reset barrier counter, seed h buffer (proven)
// ===========================================================================
__global__ void init_kernel(const float* __restrict__ h1) {
    int i = threadIdx.x;   // 1024 threads
    if (i == 0) g_cnt = 0;
    g_h[0][i] = h1[i];
}

// ===========================================================================
// Barrier primitives (proven)
// ===========================================================================
__device__ __forceinline__ void red_release_add1(int* p) {
    asm volatile("red.release.gpu.global.add.s32 [%0], 1;" :: "l"(p) : "memory");
}
__device__ __forceinline__ int ld_acquire(const int* p) {
    int v;
    asm volatile("ld.acquire.gpu.global.b32 %0, [%1];" : "=r"(v) : "l"(p) : "memory");
    return v;
}

// Fast saturating activations (exact at +-inf; rel err ~1e-6)
__device__ __forceinline__ float sig_fast(float x) {
    return __fdividef(1.0f, 1.0f + __expf(-x));
}
__device__ __forceinline__ float tanh_fast(float x) {
    return 1.0f - __fdividef(2.0f, __expf(2.0f * x) + 1.0f);
}

// ===========================================================================
// Persistent LSTM recurrence. 128 CTAs x 512 threads; W_hh in registers;
// per-warp h slab loads; 2-acc dot; counter barrier; CTA-0 fc tail.
// Round 17: TWO block syncs per step — the middle __syncthreads between
// warp-0's h stores and tid0's RED is replaced by __syncwarp() (all those
// stores are in warp 0; syncwarp gives the hb edge into the release).
// ===========================================================================
__global__ void __launch_bounds__(512, 1) lstm_rec_kernel(
    const float* __restrict__ W_hh,   // [4096,1024]
    const float* __restrict__ c1,     // [1024]
    const float* __restrict__ b_hh,   // [4096]
    const float* __restrict__ fc_w,   // [32,1024]
    const float* __restrict__ fc_b,   // [32]
    float* __restrict__ out,          // d_out
    int writeHC)
{
    __shared__ __align__(16) float hsm[HID];
    __shared__ float psum[16][33];

    const int tid = threadIdx.x;
    const int bid = blockIdx.x;
    const int w = tid >> 5;
    const int l = tid & 31;
    const int u = l >> 2;
    const int g = l & 3;
    const int gate_row = g * HID + bid * UPB + u;

    // ---- W_hh slab into registers: 32 f32x2 per thread ----
    unsigned long long wreg[32];
    {
        const float* wp = W_hh + (size_t)gate_row * HID + w * 64;
#pragma unroll
        for (int k = 0; k < 32; k++)
            wreg[k] = *(const unsigned long long*)(wp + 2 * k);
    }

    // ---- warp-0 per-lane state ----
    float bias = 0.f, xg = 0.f, c = 0.f;
    if (w == 0) {
        bias = b_hh[gate_row];
        xg   = __ldg(g_xg + gate_row);       // row t=0
        if (g == 0) c = c1[bid * UPB + u];
    }
    __syncthreads();

    for (int t = 0; t < WINDOW; t++) {
        const int p = t & 1;

        // ---- each warp loads its OWN 64-float h slab (no block sync) ----
        if (l < 16)
            ((float4*)(hsm + w * 64))[l] =
                __ldcg(((const float4*)g_h[p]) + w * 16 + l);
        __syncwarp();

        // ---- 64-col partial dot: 2 accumulators ----
        unsigned long long acc0 = 0ull, acc1 = 0ull;
        const unsigned long long* hp = (const unsigned long long*)(hsm + w * 64);
#pragma unroll
        for (int k = 0; k < 16; k++) {
            fma2(acc0, wreg[2 * k],     hp[2 * k]);
            fma2(acc1, wreg[2 * k + 1], hp[2 * k + 1]);
        }
        {
            unsigned int x0, y0, x1, y1;
            asm("mov.b64 {%0, %1}, %2;" : "=r"(x0), "=r"(y0) : "l"(acc0));
            asm("mov.b64 {%0, %1}, %2;" : "=r"(x1), "=r"(y1) : "l"(acc1));
            psum[w][l] = (__uint_as_float(x0) + __uint_as_float(y0))
                       + (__uint_as_float(x1) + __uint_as_float(y1));
        }
        __syncthreads();                         // psum ready for warp 0

        // ---- warp 0: reduce, gates, h store, then barrier arrival+poll ----
        if (w == 0) {
            float pre = xg + bias;
#pragma unroll
            for (int q = 0; q < 16; q++) pre += psum[q][l];

            float a = (g == 2) ? tanh_fast(pre) : sig_fast(pre);
            int base = l & ~3;
            float fg = __shfl_sync(0xffffffffu, a, base + 1);
            float gb = __shfl_sync(0xffffffffu, a, base + 2);
            float og = __shfl_sync(0xffffffffu, a, base + 3);
            if (g == 0) {
                c = fg * c + a * gb;
                float hn = og * tanh_fast(c);
                int jj = bid * UPB + u;
                g_h[p ^ 1][jj] = hn;
                if (writeHC && t == 1023) {          // STRIDE-1
                    out[METRIC + jj] = hn;
                    out[METRIC + HID + jj] = c;
                }
            }
            // prefetch next step's xg (hides L2 latency under the barrier)
            if (t + 1 < WINDOW)
                xg = __ldg(g_xg + (size_t)(t + 1) * GATE4 + gate_row);

            // order ALL warp-0 lanes' h stores before tid0's release-RED
            __syncwarp();
            if (l == 0) {
                red_release_add1(&g_cnt);
                const int target = (t + 1) * NCTA;
                while (ld_acquire(&g_cnt) < target) { }
            }
        }
        __syncthreads();                         // single end-of-step barrier
    }

    // ---- fc epilogue folded in: CTA 0 only, h_fin = g_h[0] ----
    if (bid == 0) {
        for (int half = 0; half < 2; half++) {
            const int m = 2 * w + half;              // metric 0..31
            const float4* wv = (const float4*)(fc_w + (size_t)m * HID);
            float s = 0.f;
#pragma unroll
            for (int jj = 0; jj < 8; jj++) {
                float4 a = __ldcg(((const float4*)g_h[0]) + l + 32 * jj);
                float4 b = __ldg(wv + l + 32 * jj);
                s += a.x * b.x + a.y * b.y + a.z * b.z + a.w * b.w;
            }
#pragma unroll
            for (int off = 16; off; off >>= 1)
                s += __shfl_xor_sync(0xffffffffu, s, off);
            if (l == 0) out[m] = tanhf(s + fc_b[m]);
        }
    }
}

// ===========================================================================
// launch — exactly 3 launches per call (gemm, init, lstm)
// ===========================================================================
extern "C" void kernel_launch(void* const* d_in, const int* in_sizes, int n_in,
                              void* d_out, int out_size) {
    const float* inp  = (const float*)d_in[0];
    const float* h1   = (const float*)d_in[1];
    const float* c1   = (const float*)d_in[2];
    const float* W_ih = (const float*)d_in[3];
    const float* W_hh = (const float*)d_in[4];
    const float* b_ih = (const float*)d_in[5];
    const float* b_hh = (const float*)d_in[6];
    const float* fc_w = (const float*)d_in[7];
    const float* fc_b = (const float*)d_in[8];
    float* out = (float*)d_out;

    int writeHC = (out_size >= METRIC + 2 * HID) ? 1 : 0;

    float* xg_ptr = nullptr;
    cudaGetSymbolAddress((void**)&xg_ptr, g_xg);

    // Phase 1: xg GEMM (8x8 micro-tile, 256 threads, double-buffered)
    dim3 ggrid(GATE4 / BN, WINDOW / BM);
    gemm_xg_kernel<<<ggrid, 256>>>(inp, W_ih, b_ih, xg_ptr);

    // Phase 1b: init h buffer + barrier counter
    init_kernel<<<1, HID>>>(h1);

    // Phase 2: persistent recurrence + folded fc epilogue
    lstm_rec_kernel<<<NCTA, 512>>>(W_hh, c1, b_hh, fc_w, fc_b, out, writeHC);
}